// round 9
// baseline (speedup 1.0000x reference)
#include <cuda_runtime.h>
#include <cuda_fp16.h>

// Problem constants (fixed by reference)
#define BB   32
#define NBX  6
#define HH   512
#define WW   512
#define PNp  512          // patch is PNp x PNp x 3
#define SCALE_F  0.5f
#define ASPECT_F 1.0f
#define MIN_PH_F 60.0f

struct __align__(16) PBox {
    int   y0, x0, h, w;
    float inv_h, inv_w;
    int   valid;
    int   pad;
};

// Quad-packed patch texel: full 2x2 bilinear footprint (clamped neighbors) fp16:
//   u[0]=(r00,r01) u[1]=(g00,g01) u[2]=(b00,b01)
//   u[3]=(r10,r11) u[4]=(g10,g11) u[5]=(b10,b11)  u[6..7]=pad
struct __align__(32) Quad { unsigned u[8]; };
__device__ Quad g_quad[PNp * PNp];       // 8 MB

// ---------------------------------------------------------------------------
// Prep: build quad-packed fp16 patch. 4 texels per thread, vectorized reads.
// ---------------------------------------------------------------------------
__global__ void __launch_bounds__(256)
prep_patch_kernel(const float* __restrict__ patch) {
    int i = blockIdx.x * blockDim.x + threadIdx.x;   // 65536 threads
    if (i >= PNp * PNp / 4) return;
    int y  = i >> 7;                    // row
    int x0 = (i & 127) << 2;            // first of 4 x positions
    int yh = min(y + 1, PNp - 1);

    // Load 5 pixels (x0..x0+4, clamped) from rows y and yh.
    // px x0..x0+3 = 12 floats = 3 float4 (16B-aligned: 12*x0 bytes? 3*x0 floats,
    // x0 multiple of 4 -> byte offset 48*x0/4*4 = 12*x0*4 ... verified: 3*x0*4 = 48k, 16 | 48k).
    float r0[15], r1[15];
    {
        const float4* p = (const float4*)(patch + ((size_t)y * PNp + x0) * 3);
        float4 a = __ldg(p + 0), b2 = __ldg(p + 1), c = __ldg(p + 2);
        r0[0]=a.x; r0[1]=a.y; r0[2]=a.z; r0[3]=a.w;
        r0[4]=b2.x; r0[5]=b2.y; r0[6]=b2.z; r0[7]=b2.w;
        r0[8]=c.x; r0[9]=c.y; r0[10]=c.z; r0[11]=c.w;
        int x4 = min(x0 + 4, PNp - 1);
        const float* e = patch + ((size_t)y * PNp + x4) * 3;
        r0[12]=__ldg(e+0); r0[13]=__ldg(e+1); r0[14]=__ldg(e+2);
    }
    {
        const float4* p = (const float4*)(patch + ((size_t)yh * PNp + x0) * 3);
        float4 a = __ldg(p + 0), b2 = __ldg(p + 1), c = __ldg(p + 2);
        r1[0]=a.x; r1[1]=a.y; r1[2]=a.z; r1[3]=a.w;
        r1[4]=b2.x; r1[5]=b2.y; r1[6]=b2.z; r1[7]=b2.w;
        r1[8]=c.x; r1[9]=c.y; r1[10]=c.z; r1[11]=c.w;
        int x4 = min(x0 + 4, PNp - 1);
        const float* e = patch + ((size_t)yh * PNp + x4) * 3;
        r1[12]=__ldg(e+0); r1[13]=__ldg(e+1); r1[14]=__ldg(e+2);
    }

    #pragma unroll
    for (int k = 0; k < 4; ++k) {
        // xh clamp: x0+k+1 <= 512; if x0+k == 511 use same pixel (k==3 of last group)
        int lo = k * 3;
        int hi = (x0 + k == PNp - 1) ? lo : lo + 3;
        __half2 rr0 = __floats2half2_rn(r0[lo + 0], r0[hi + 0]);
        __half2 gg0 = __floats2half2_rn(r0[lo + 1], r0[hi + 1]);
        __half2 bb0 = __floats2half2_rn(r0[lo + 2], r0[hi + 2]);
        __half2 rr1 = __floats2half2_rn(r1[lo + 0], r1[hi + 0]);
        __half2 gg1 = __floats2half2_rn(r1[lo + 1], r1[hi + 1]);
        __half2 bb1 = __floats2half2_rn(r1[lo + 2], r1[hi + 2]);
        Quad q;
        q.u[0] = *(const unsigned*)&rr0;
        q.u[1] = *(const unsigned*)&gg0;
        q.u[2] = *(const unsigned*)&bb0;
        q.u[3] = *(const unsigned*)&rr1;
        q.u[4] = *(const unsigned*)&gg1;
        q.u[5] = *(const unsigned*)&bb1;
        q.u[6] = 0; q.u[7] = 0;
        g_quad[y * PNp + x0 + k] = q;
    }
}

// 256-bit loads/stores (sm_100+)
__device__ __forceinline__ void ldg256_nc(const void* p, unsigned r[8]) {
    asm volatile("ld.global.nc.v8.b32 {%0,%1,%2,%3,%4,%5,%6,%7}, [%8];"
                 : "=r"(r[0]), "=r"(r[1]), "=r"(r[2]), "=r"(r[3]),
                   "=r"(r[4]), "=r"(r[5]), "=r"(r[6]), "=r"(r[7])
                 : "l"(p));
}
__device__ __forceinline__ void ldg256_cs(const void* p, float r[8]) {
    asm volatile("ld.global.cs.v8.f32 {%0,%1,%2,%3,%4,%5,%6,%7}, [%8];"
                 : "=f"(r[0]), "=f"(r[1]), "=f"(r[2]), "=f"(r[3]),
                   "=f"(r[4]), "=f"(r[5]), "=f"(r[6]), "=f"(r[7])
                 : "l"(p));
}
__device__ __forceinline__ void stg256_cs(void* p, const float r[8]) {
    asm volatile("st.global.cs.v8.f32 [%0], {%1,%2,%3,%4,%5,%6,%7,%8};"
                 :: "l"(p),
                    "f"(r[0]), "f"(r[1]), "f"(r[2]), "f"(r[3]),
                    "f"(r[4]), "f"(r[5]), "f"(r[6]), "f"(r[7])
                 : "memory");
}

// ---------------------------------------------------------------------------
// Main: one thread per 8 consecutive pixels (24 floats = 3 x 256-bit).
// Each block covers 2048 contiguous pixels of ONE image (128 blocks/image).
// ---------------------------------------------------------------------------
__global__ void __launch_bounds__(256, 6)
paste_kernel(const float* __restrict__ img,
             const float* __restrict__ boxes,
             float* __restrict__ out) {
    __shared__ PBox sbox[NBX];
    int b = blockIdx.x >> 7;           // 128 blocks per image
    if (threadIdx.x < NBX) {
        const float* bx = boxes + ((size_t)b * NBX + threadIdx.x) * 4;
        float ymin = __ldg(bx + 0), xmin = __ldg(bx + 1);
        float ymax = __ldg(bx + 2), xmax = __ldg(bx + 3);
        float h = ymax - ymin;
        float w = xmax - xmin;
        float pw = h * SCALE_F;
        float ph = ASPECT_F * pw;
        float oy = ymin + h * 0.5f;
        float ox = xmin + w * 0.5f;
        float yp = fmaxf(oy - ph * 0.5f, 0.0f);
        float xp = fmaxf(ox - pw * 0.5f, 0.0f);
        if (yp + ph > (float)HH) yp = (float)HH - ph;
        if (xp + pw > (float)WW) xp = (float)WW - pw;
        PBox pb;
        pb.y0 = (int)yp;
        pb.x0 = (int)xp;
        pb.h  = (int)ph;
        pb.w  = (int)pw;
        pb.inv_h = (float)PNp / fmaxf((float)pb.h, 1.0f);
        pb.inv_w = (float)PNp / fmaxf((float)pb.w, 1.0f);
        pb.valid = (ph > MIN_PH_F) ? 1 : 0;
        pb.pad = 0;
        sbox[threadIdx.x] = pb;
    }
    __syncthreads();

    int t  = blockIdx.x * blockDim.x + threadIdx.x;
    int p0 = t << 3;                   // first pixel index (8 per thread)
    int rem = p0 & ((1 << 18) - 1);    // within-image index
    int y   = rem >> 9;                // W = 2^9
    int x   = rem & (WW - 1);          // multiple of 8, within one row

    // Find topmost covering box per pixel
    int cov[8];
    #pragma unroll
    for (int k = 0; k < 8; ++k) cov[k] = -1;
    #pragma unroll
    for (int n = NBX - 1; n >= 0; --n) {
        PBox pb = sbox[n];
        if (!pb.valid) continue;
        int dy = y - pb.y0;
        if ((unsigned)dy >= (unsigned)pb.h) continue;
        int dx0 = x - pb.x0;
        #pragma unroll
        for (int k = 0; k < 8; ++k) {
            if (cov[k] < 0 && (unsigned)(dx0 + k) < (unsigned)pb.w) cov[k] = n;
        }
    }

    float px[24];                       // 8 px * rgb, pixel-major
    bool anyuncov = false;
    #pragma unroll
    for (int k = 0; k < 8; ++k) anyuncov |= (cov[k] < 0);

    const float* ibase = img + (size_t)p0 * 3;
    if (anyuncov) {
        ldg256_cs(ibase +  0, px +  0);
        ldg256_cs(ibase +  8, px +  8);
        ldg256_cs(ibase + 16, px + 16);
    }

    #pragma unroll
    for (int k = 0; k < 8; ++k) {
        if (cov[k] < 0) continue;
        PBox pb = sbox[cov[k]];
        int dy = y - pb.y0;
        int dx = (x + k) - pb.x0;

        float sy = ((float)dy + 0.5f) * pb.inv_h - 0.5f;
        float sx = ((float)dx + 0.5f) * pb.inv_w - 0.5f;
        sy = fminf(fmaxf(sy, 0.0f), (float)(PNp - 1));
        sx = fminf(fmaxf(sx, 0.0f), (float)(PNp - 1));

        int   yl = (int)floorf(sy);
        int   xl = (int)floorf(sx);
        float wy = sy - (float)yl;
        float wx = sx - (float)xl;

        unsigned q[8];
        ldg256_nc(&g_quad[yl * PNp + xl], q);

        float2 r0 = __half22float2(*(const __half2*)&q[0]);  // (r00, r01)
        float2 g0 = __half22float2(*(const __half2*)&q[1]);
        float2 b0 = __half22float2(*(const __half2*)&q[2]);
        float2 r1 = __half22float2(*(const __half2*)&q[3]);  // (r10, r11)
        float2 g1 = __half22float2(*(const __half2*)&q[4]);
        float2 b1 = __half22float2(*(const __half2*)&q[5]);

        float omwy = 1.0f - wy;
        float omwx = 1.0f - wx;
        float rlo = r0.x * omwy + r1.x * wy;
        float rhi = r0.y * omwy + r1.y * wy;
        float glo = g0.x * omwy + g1.x * wy;
        float ghi = g0.y * omwy + g1.y * wy;
        float blo = b0.x * omwy + b1.x * wy;
        float bhi = b0.y * omwy + b1.y * wy;
        px[k * 3 + 0] = rlo * omwx + rhi * wx;
        px[k * 3 + 1] = glo * omwx + ghi * wx;
        px[k * 3 + 2] = blo * omwx + bhi * wx;
    }

    float* obase = out + (size_t)p0 * 3;
    stg256_cs(obase +  0, px +  0);
    stg256_cs(obase +  8, px +  8);
    stg256_cs(obase + 16, px + 16);
}

extern "C" void kernel_launch(void* const* d_in, const int* in_sizes, int n_in,
                              void* d_out, int out_size) {
    const float* images = (const float*)d_in[0];   // [32,512,512,3] f32
    const float* boxes  = (const float*)d_in[1];   // [32,6,4] f32
    const float* patch  = (const float*)d_in[2];   // [512,512,3] f32
    float* out = (float*)d_out;

    prep_patch_kernel<<<(PNp * PNp / 4) / 256, 256>>>(patch);

    const int total = BB * HH * WW / 8;            // 1,048,576 threads
    paste_kernel<<<total / 256, 256>>>(images, boxes, out);
}

// round 12
// speedup vs baseline: 1.0069x; 1.0069x over previous
#include <cuda_runtime.h>
#include <cuda_fp16.h>

// Problem constants (fixed by reference)
#define BB   32
#define NBX  6
#define HH   512
#define WW   512
#define PNp  512          // patch is PNp x PNp x 3
#define SCALE_F  0.5f
#define ASPECT_F 1.0f
#define MIN_PH_F 60.0f

struct __align__(16) PBox {
    int   y0, x0, h, w;
    float inv_h, inv_w;
    int   valid;
    int   pad;
};

// Quad-packed patch texel: full 2x2 bilinear footprint (clamped neighbors) fp16:
//   u[0]=(r00,r01) u[1]=(g00,g01) u[2]=(b00,b01)
//   u[3]=(r10,r11) u[4]=(g10,g11) u[5]=(b10,b11)  u[6..7]=pad (never read by math)
struct __align__(32) Quad { unsigned u[8]; };
__device__ Quad g_quad[PNp * PNp];       // 8 MB

// ---------------------------------------------------------------------------
// Prep: build quad-packed fp16 patch. One texel per thread, static indexing.
// ---------------------------------------------------------------------------
__global__ void __launch_bounds__(256)
prep_patch_kernel(const float* __restrict__ patch) {
    int i = blockIdx.x * blockDim.x + threadIdx.x;   // i = y*512 + x
    if (i >= PNp * PNp) return;
    int y  = i >> 9;
    int x  = i & (PNp - 1);
    int yh = min(y + 1, PNp - 1);
    int xh = min(x + 1, PNp - 1);

    const float* p00 = patch + ((size_t)y  * PNp + x ) * 3;
    const float* p01 = patch + ((size_t)y  * PNp + xh) * 3;
    const float* p10 = patch + ((size_t)yh * PNp + x ) * 3;
    const float* p11 = patch + ((size_t)yh * PNp + xh) * 3;

    __half2 r0 = __floats2half2_rn(__ldg(p00 + 0), __ldg(p01 + 0));
    __half2 g0 = __floats2half2_rn(__ldg(p00 + 1), __ldg(p01 + 1));
    __half2 b0 = __floats2half2_rn(__ldg(p00 + 2), __ldg(p01 + 2));
    __half2 r1 = __floats2half2_rn(__ldg(p10 + 0), __ldg(p11 + 0));
    __half2 g1 = __floats2half2_rn(__ldg(p10 + 1), __ldg(p11 + 1));
    __half2 b1 = __floats2half2_rn(__ldg(p10 + 2), __ldg(p11 + 2));

    uint4 lo;
    lo.x = *(const unsigned*)&r0;
    lo.y = *(const unsigned*)&g0;
    lo.z = *(const unsigned*)&b0;
    lo.w = *(const unsigned*)&r1;
    uint2 hi;
    hi.x = *(const unsigned*)&g1;
    hi.y = *(const unsigned*)&b1;
    *(uint4*)(&g_quad[i].u[0]) = lo;     // 16 B
    *(uint2*)(&g_quad[i].u[4]) = hi;     // 8 B (pad words left undefined)
}

// 256-bit loads/stores (sm_100+)
__device__ __forceinline__ void ldg256_nc(const void* p, unsigned r[8]) {
    asm volatile("ld.global.nc.v8.b32 {%0,%1,%2,%3,%4,%5,%6,%7}, [%8];"
                 : "=r"(r[0]), "=r"(r[1]), "=r"(r[2]), "=r"(r[3]),
                   "=r"(r[4]), "=r"(r[5]), "=r"(r[6]), "=r"(r[7])
                 : "l"(p));
}
__device__ __forceinline__ void ldg256_cs(const void* p, float r[8]) {
    asm volatile("ld.global.cs.v8.f32 {%0,%1,%2,%3,%4,%5,%6,%7}, [%8];"
                 : "=f"(r[0]), "=f"(r[1]), "=f"(r[2]), "=f"(r[3]),
                   "=f"(r[4]), "=f"(r[5]), "=f"(r[6]), "=f"(r[7])
                 : "l"(p));
}
__device__ __forceinline__ void stg256_cs(void* p, const float r[8]) {
    asm volatile("st.global.cs.v8.f32 [%0], {%1,%2,%3,%4,%5,%6,%7,%8};"
                 :: "l"(p),
                    "f"(r[0]), "f"(r[1]), "f"(r[2]), "f"(r[3]),
                    "f"(r[4]), "f"(r[5]), "f"(r[6]), "f"(r[7])
                 : "memory");
}

// ---------------------------------------------------------------------------
// Main: one thread per 8 consecutive pixels (24 floats = 3 x 256-bit).
// Each block covers 2048 contiguous pixels of ONE image (128 blocks/image).
// Gather loop is branch-free (clamped index + select) so the 8 LDG.256s can
// be batched for memory-level parallelism.
// ---------------------------------------------------------------------------
__global__ void __launch_bounds__(256)
paste_kernel(const float* __restrict__ img,
             const float* __restrict__ boxes,
             float* __restrict__ out) {
    __shared__ PBox sbox[NBX];
    int b = blockIdx.x >> 7;           // 128 blocks per image
    if (threadIdx.x < NBX) {
        const float* bx = boxes + ((size_t)b * NBX + threadIdx.x) * 4;
        float ymin = __ldg(bx + 0), xmin = __ldg(bx + 1);
        float ymax = __ldg(bx + 2), xmax = __ldg(bx + 3);
        float h = ymax - ymin;
        float w = xmax - xmin;
        float pw = h * SCALE_F;
        float ph = ASPECT_F * pw;
        float oy = ymin + h * 0.5f;
        float ox = xmin + w * 0.5f;
        float yp = fmaxf(oy - ph * 0.5f, 0.0f);
        float xp = fmaxf(ox - pw * 0.5f, 0.0f);
        if (yp + ph > (float)HH) yp = (float)HH - ph;
        if (xp + pw > (float)WW) xp = (float)WW - pw;
        PBox pb;
        pb.y0 = (int)yp;
        pb.x0 = (int)xp;
        pb.h  = (int)ph;
        pb.w  = (int)pw;
        pb.inv_h = (float)PNp / fmaxf((float)pb.h, 1.0f);
        pb.inv_w = (float)PNp / fmaxf((float)pb.w, 1.0f);
        pb.valid = (ph > MIN_PH_F) ? 1 : 0;
        pb.pad = 0;
        sbox[threadIdx.x] = pb;
    }
    __syncthreads();

    int t  = blockIdx.x * blockDim.x + threadIdx.x;
    int p0 = t << 3;                   // first pixel index (8 per thread)
    int rem = p0 & ((1 << 18) - 1);    // within-image index
    int y   = rem >> 9;                // W = 2^9
    int x   = rem & (WW - 1);          // multiple of 8, within one row

    // Find topmost covering box per pixel
    int cov[8];
    #pragma unroll
    for (int k = 0; k < 8; ++k) cov[k] = -1;
    #pragma unroll
    for (int n = NBX - 1; n >= 0; --n) {
        PBox pb = sbox[n];
        if (!pb.valid) continue;
        int dy = y - pb.y0;
        if ((unsigned)dy >= (unsigned)pb.h) continue;
        int dx0 = x - pb.x0;
        #pragma unroll
        for (int k = 0; k < 8; ++k) {
            if (cov[k] < 0 && (unsigned)(dx0 + k) < (unsigned)pb.w) cov[k] = n;
        }
    }

    float px[24];                       // 8 px * rgb, pixel-major
    bool anyuncov = false, anycov = false;
    #pragma unroll
    for (int k = 0; k < 8; ++k) { anyuncov |= (cov[k] < 0); anycov |= (cov[k] >= 0); }

    const float* ibase = img + (size_t)p0 * 3;
    if (anyuncov) {
        ldg256_cs(ibase +  0, px +  0);
        ldg256_cs(ibase +  8, px +  8);
        ldg256_cs(ibase + 16, px + 16);
    }

    if (anycov) {
        #pragma unroll
        for (int k = 0; k < 8; ++k) {
            int  c       = cov[k];
            bool covered = (c >= 0);
            PBox pb = sbox[covered ? c : 0];
            int dy = y - pb.y0;
            int dx = (x + k) - pb.x0;

            float sy = ((float)dy + 0.5f) * pb.inv_h - 0.5f;
            float sx = ((float)dx + 0.5f) * pb.inv_w - 0.5f;
            sy = fminf(fmaxf(sy, 0.0f), (float)(PNp - 1));
            sx = fminf(fmaxf(sx, 0.0f), (float)(PNp - 1));

            int   yl = (int)floorf(sy);
            int   xl = (int)floorf(sx);
            float wy = sy - (float)yl;
            float wx = sx - (float)xl;

            int idx = covered ? (yl * PNp + xl) : 0;   // broadcast line if uncovered
            unsigned q[8];
            ldg256_nc(&g_quad[idx], q);

            float2 r0 = __half22float2(*(const __half2*)&q[0]);  // (r00, r01)
            float2 g0 = __half22float2(*(const __half2*)&q[1]);
            float2 b0 = __half22float2(*(const __half2*)&q[2]);
            float2 r1 = __half22float2(*(const __half2*)&q[3]);  // (r10, r11)
            float2 g1 = __half22float2(*(const __half2*)&q[4]);
            float2 b1 = __half22float2(*(const __half2*)&q[5]);

            float omwy = 1.0f - wy;
            float omwx = 1.0f - wx;
            float rlo = r0.x * omwy + r1.x * wy;
            float rhi = r0.y * omwy + r1.y * wy;
            float glo = g0.x * omwy + g1.x * wy;
            float ghi = g0.y * omwy + g1.y * wy;
            float blo = b0.x * omwy + b1.x * wy;
            float bhi = b0.y * omwy + b1.y * wy;
            float vr = rlo * omwx + rhi * wx;
            float vg = glo * omwx + ghi * wx;
            float vb = blo * omwx + bhi * wx;

            px[k * 3 + 0] = covered ? vr : px[k * 3 + 0];
            px[k * 3 + 1] = covered ? vg : px[k * 3 + 1];
            px[k * 3 + 2] = covered ? vb : px[k * 3 + 2];
        }
    }

    float* obase = out + (size_t)p0 * 3;
    stg256_cs(obase +  0, px +  0);
    stg256_cs(obase +  8, px +  8);
    stg256_cs(obase + 16, px + 16);
}

extern "C" void kernel_launch(void* const* d_in, const int* in_sizes, int n_in,
                              void* d_out, int out_size) {
    const float* images = (const float*)d_in[0];   // [32,512,512,3] f32
    const float* boxes  = (const float*)d_in[1];   // [32,6,4] f32
    const float* patch  = (const float*)d_in[2];   // [512,512,3] f32
    float* out = (float*)d_out;

    prep_patch_kernel<<<(PNp * PNp) / 256, 256>>>(patch);

    const int total = BB * HH * WW / 8;            // 1,048,576 threads
    paste_kernel<<<total / 256, 256>>>(images, boxes, out);
}

// round 13
// speedup vs baseline: 1.0728x; 1.0655x over previous
#include <cuda_runtime.h>
#include <cuda_fp16.h>

// Problem constants (fixed by reference)
#define BB   32
#define NBX  6
#define HH   512
#define WW   512
#define PNp  512          // patch is PNp x PNp x 3
#define SCALE_F  0.5f
#define ASPECT_F 1.0f
#define MIN_PH_F 60.0f

struct __align__(16) PBox {
    int   y0, x0, h, w;
    float inv_h, inv_w;
    int   valid;
    int   pad;
};

// Quad-packed patch texel: full 2x2 bilinear footprint (clamped neighbors) fp16:
//   u[0]=(r00,r01) u[1]=(g00,g01) u[2]=(b00,b01)
//   u[3]=(r10,r11) u[4]=(g10,g11) u[5]=(b10,b11)  u[6..7]=pad (never read)
struct __align__(32) Quad { unsigned u[8]; };
__device__ Quad g_quad[PNp * PNp];       // 8 MB

// ---------------------------------------------------------------------------
// Prep: build quad-packed fp16 patch. One texel per thread, static indexing.
// ---------------------------------------------------------------------------
__global__ void __launch_bounds__(256)
prep_patch_kernel(const float* __restrict__ patch) {
    int i = blockIdx.x * blockDim.x + threadIdx.x;   // i = y*512 + x
    if (i >= PNp * PNp) return;
    int y  = i >> 9;
    int x  = i & (PNp - 1);
    int yh = min(y + 1, PNp - 1);
    int xh = min(x + 1, PNp - 1);

    const float* p00 = patch + ((size_t)y  * PNp + x ) * 3;
    const float* p01 = patch + ((size_t)y  * PNp + xh) * 3;
    const float* p10 = patch + ((size_t)yh * PNp + x ) * 3;
    const float* p11 = patch + ((size_t)yh * PNp + xh) * 3;

    __half2 r0 = __floats2half2_rn(__ldg(p00 + 0), __ldg(p01 + 0));
    __half2 g0 = __floats2half2_rn(__ldg(p00 + 1), __ldg(p01 + 1));
    __half2 b0 = __floats2half2_rn(__ldg(p00 + 2), __ldg(p01 + 2));
    __half2 r1 = __floats2half2_rn(__ldg(p10 + 0), __ldg(p11 + 0));
    __half2 g1 = __floats2half2_rn(__ldg(p10 + 1), __ldg(p11 + 1));
    __half2 b1 = __floats2half2_rn(__ldg(p10 + 2), __ldg(p11 + 2));

    uint4 lo;
    lo.x = *(const unsigned*)&r0;
    lo.y = *(const unsigned*)&g0;
    lo.z = *(const unsigned*)&b0;
    lo.w = *(const unsigned*)&r1;
    uint2 hi;
    hi.x = *(const unsigned*)&g1;
    hi.y = *(const unsigned*)&b1;
    *(uint4*)(&g_quad[i].u[0]) = lo;     // 16 B
    *(uint2*)(&g_quad[i].u[4]) = hi;     // 8 B
}

// 256-bit loads/stores (sm_100+)
__device__ __forceinline__ void ldg256_nc(const void* p, unsigned r[8]) {
    asm volatile("ld.global.nc.v8.b32 {%0,%1,%2,%3,%4,%5,%6,%7}, [%8];"
                 : "=r"(r[0]), "=r"(r[1]), "=r"(r[2]), "=r"(r[3]),
                   "=r"(r[4]), "=r"(r[5]), "=r"(r[6]), "=r"(r[7])
                 : "l"(p));
}
__device__ __forceinline__ void ldg256_cs(const void* p, float r[8]) {
    asm volatile("ld.global.cs.v8.f32 {%0,%1,%2,%3,%4,%5,%6,%7}, [%8];"
                 : "=f"(r[0]), "=f"(r[1]), "=f"(r[2]), "=f"(r[3]),
                   "=f"(r[4]), "=f"(r[5]), "=f"(r[6]), "=f"(r[7])
                 : "l"(p));
}
__device__ __forceinline__ void stg256_cs(void* p, const float r[8]) {
    asm volatile("st.global.cs.v8.f32 [%0], {%1,%2,%3,%4,%5,%6,%7,%8};"
                 :: "l"(p),
                    "f"(r[0]), "f"(r[1]), "f"(r[2]), "f"(r[3]),
                    "f"(r[4]), "f"(r[5]), "f"(r[6]), "f"(r[7])
                 : "memory");
}

// Bilinear from a quad record (already-loaded regs) into 3 floats.
__device__ __forceinline__ void quad_lerp(const unsigned q[8], float wy, float wx,
                                          float* outr, float* outg, float* outb) {
    float2 r0 = __half22float2(*(const __half2*)&q[0]);  // (r00, r01)
    float2 g0 = __half22float2(*(const __half2*)&q[1]);
    float2 b0 = __half22float2(*(const __half2*)&q[2]);
    float2 r1 = __half22float2(*(const __half2*)&q[3]);  // (r10, r11)
    float2 g1 = __half22float2(*(const __half2*)&q[4]);
    float2 b1 = __half22float2(*(const __half2*)&q[5]);
    float omwy = 1.0f - wy;
    float omwx = 1.0f - wx;
    float rlo = r0.x * omwy + r1.x * wy;
    float rhi = r0.y * omwy + r1.y * wy;
    float glo = g0.x * omwy + g1.x * wy;
    float ghi = g0.y * omwy + g1.y * wy;
    float blo = b0.x * omwy + b1.x * wy;
    float bhi = b0.y * omwy + b1.y * wy;
    *outr = rlo * omwx + rhi * wx;
    *outg = glo * omwx + ghi * wx;
    *outb = blo * omwx + bhi * wx;
}

// ---------------------------------------------------------------------------
// Main: one thread per 8 consecutive pixels (24 floats = 3 x 256-bit).
// Each block covers 2048 contiguous pixels of ONE image (128 blocks/image).
// Covered-pixel gathers processed in PAIRS: two independent LDG.256 issued
// before either is consumed -> 2x memory-level parallelism on the L2 path.
// ---------------------------------------------------------------------------
__global__ void __launch_bounds__(256)
paste_kernel(const float* __restrict__ img,
             const float* __restrict__ boxes,
             float* __restrict__ out) {
    __shared__ PBox sbox[NBX];
    int b = blockIdx.x >> 7;           // 128 blocks per image
    if (threadIdx.x < NBX) {
        const float* bx = boxes + ((size_t)b * NBX + threadIdx.x) * 4;
        float ymin = __ldg(bx + 0), xmin = __ldg(bx + 1);
        float ymax = __ldg(bx + 2), xmax = __ldg(bx + 3);
        float h = ymax - ymin;
        float w = xmax - xmin;
        float pw = h * SCALE_F;
        float ph = ASPECT_F * pw;
        float oy = ymin + h * 0.5f;
        float ox = xmin + w * 0.5f;
        float yp = fmaxf(oy - ph * 0.5f, 0.0f);
        float xp = fmaxf(ox - pw * 0.5f, 0.0f);
        if (yp + ph > (float)HH) yp = (float)HH - ph;
        if (xp + pw > (float)WW) xp = (float)WW - pw;
        PBox pb;
        pb.y0 = (int)yp;
        pb.x0 = (int)xp;
        pb.h  = (int)ph;
        pb.w  = (int)pw;
        pb.inv_h = (float)PNp / fmaxf((float)pb.h, 1.0f);
        pb.inv_w = (float)PNp / fmaxf((float)pb.w, 1.0f);
        pb.valid = (ph > MIN_PH_F) ? 1 : 0;
        pb.pad = 0;
        sbox[threadIdx.x] = pb;
    }
    __syncthreads();

    int t  = blockIdx.x * blockDim.x + threadIdx.x;
    int p0 = t << 3;                   // first pixel index (8 per thread)
    int rem = p0 & ((1 << 18) - 1);    // within-image index
    int y   = rem >> 9;                // W = 2^9
    int x   = rem & (WW - 1);          // multiple of 8, within one row

    // Find topmost covering box per pixel
    int cov[8];
    #pragma unroll
    for (int k = 0; k < 8; ++k) cov[k] = -1;
    #pragma unroll
    for (int n = NBX - 1; n >= 0; --n) {
        PBox pb = sbox[n];
        if (!pb.valid) continue;
        int dy = y - pb.y0;
        if ((unsigned)dy >= (unsigned)pb.h) continue;
        int dx0 = x - pb.x0;
        #pragma unroll
        for (int k = 0; k < 8; ++k) {
            if (cov[k] < 0 && (unsigned)(dx0 + k) < (unsigned)pb.w) cov[k] = n;
        }
    }

    float px[24];                       // 8 px * rgb, pixel-major
    bool anyuncov = false;
    #pragma unroll
    for (int k = 0; k < 8; ++k) anyuncov |= (cov[k] < 0);

    const float* ibase = img + (size_t)p0 * 3;
    if (anyuncov) {
        ldg256_cs(ibase +  0, px +  0);
        ldg256_cs(ibase +  8, px +  8);
        ldg256_cs(ibase + 16, px + 16);
    }

    #pragma unroll
    for (int c = 0; c < 8; c += 2) {
        bool cv0 = (cov[c]     >= 0);
        bool cv1 = (cov[c + 1] >= 0);
        if (!(cv0 | cv1)) continue;

        // --- compute both addresses + weights first (pure ALU) ---
        PBox pb0 = sbox[cv0 ? cov[c]     : 0];
        PBox pb1 = sbox[cv1 ? cov[c + 1] : 0];

        float sy0 = ((float)(y - pb0.y0) + 0.5f) * pb0.inv_h - 0.5f;
        float sx0 = ((float)(x + c     - pb0.x0) + 0.5f) * pb0.inv_w - 0.5f;
        float sy1 = ((float)(y - pb1.y0) + 0.5f) * pb1.inv_h - 0.5f;
        float sx1 = ((float)(x + c + 1 - pb1.x0) + 0.5f) * pb1.inv_w - 0.5f;
        sy0 = fminf(fmaxf(sy0, 0.0f), (float)(PNp - 1));
        sx0 = fminf(fmaxf(sx0, 0.0f), (float)(PNp - 1));
        sy1 = fminf(fmaxf(sy1, 0.0f), (float)(PNp - 1));
        sx1 = fminf(fmaxf(sx1, 0.0f), (float)(PNp - 1));

        int yl0 = (int)floorf(sy0), xl0 = (int)floorf(sx0);
        int yl1 = (int)floorf(sy1), xl1 = (int)floorf(sx1);
        float wy0 = sy0 - (float)yl0, wx0 = sx0 - (float)xl0;
        float wy1 = sy1 - (float)yl1, wx1 = sx1 - (float)xl1;

        // --- issue both independent loads back-to-back ---
        unsigned q0[8], q1[8];
        if (cv0) ldg256_nc(&g_quad[yl0 * PNp + xl0], q0);
        if (cv1) ldg256_nc(&g_quad[yl1 * PNp + xl1], q1);

        // --- consume ---
        if (cv0) quad_lerp(q0, wy0, wx0, &px[c*3 + 0], &px[c*3 + 1], &px[c*3 + 2]);
        if (cv1) quad_lerp(q1, wy1, wx1, &px[c*3 + 3], &px[c*3 + 4], &px[c*3 + 5]);
    }

    float* obase = out + (size_t)p0 * 3;
    stg256_cs(obase +  0, px +  0);
    stg256_cs(obase +  8, px +  8);
    stg256_cs(obase + 16, px + 16);
}

extern "C" void kernel_launch(void* const* d_in, const int* in_sizes, int n_in,
                              void* d_out, int out_size) {
    const float* images = (const float*)d_in[0];   // [32,512,512,3] f32
    const float* boxes  = (const float*)d_in[1];   // [32,6,4] f32
    const float* patch  = (const float*)d_in[2];   // [512,512,3] f32
    float* out = (float*)d_out;

    prep_patch_kernel<<<(PNp * PNp) / 256, 256>>>(patch);

    const int total = BB * HH * WW / 8;            // 1,048,576 threads
    paste_kernel<<<total / 256, 256>>>(images, boxes, out);
}